// round 2
// baseline (speedup 1.0000x reference)
#include <cuda_runtime.h>
#include <math.h>

// ---------------- output layout (tuple order: logits, h2, alpha_t) ----------
#define LOGITS_OFF 0        // 64*128
#define H2_OFF     8192     // 64*256
#define ALPHA_OFF  24576    // 64*1024

// ---------------- scratch (device globals; no allocation allowed) -----------
__device__ float g_emb  [64 * 256];
__device__ float g_pred [64 * 256];
__device__ float g_query[64 * 512];
__device__ float g_B    [816 * 512];   // [k][n]: k<684 = Ua^T, 684..804 = W2, rest 0
__device__ float g_ep   [2][64 * 1024]; // partial e per n-chunk (deterministic merge)
__device__ float g_ctx  [64 * 684];

// ---------------- helpers ----------------------------------------------------
__device__ __forceinline__ float warp_sum(float v) {
#pragma unroll
    for (int o = 16; o; o >>= 1) v += __shfl_down_sync(0xffffffffu, v, o);
    return v;
}
__device__ __forceinline__ float sigmoidf(float x) { return 1.f / (1.f + expf(-x)); }
__device__ __forceinline__ float dot4(float4 a, float4 b) {
    return a.x * b.x + a.y * b.y + a.z * b.z + a.w * b.w;
}
// packed f32x2 FMA (sm_100+/sm_103a): 2 FMAs per instruction on the fma pipe
__device__ __forceinline__ unsigned long long pack2(float x, float y) {
    unsigned long long r;
    asm("mov.b64 %0, {%1, %2};" : "=l"(r)
        : "r"(__float_as_uint(x)), "r"(__float_as_uint(y)));
    return r;
}
__device__ __forceinline__ void fma2(unsigned long long& d, unsigned long long a,
                                     unsigned long long b) {
    asm("fma.rn.f32x2 %0, %1, %2, %0;" : "+l"(d) : "l"(a), "l"(b));
}
__device__ __forceinline__ float2 unpack2(unsigned long long v) {
    unsigned int lo, hi;
    asm("mov.b64 {%0, %1}, %2;" : "=r"(lo), "=r"(hi) : "l"(v));
    return make_float2(__uint_as_float(lo), __uint_as_float(hi));
}

// ---------------- K1: embedding lookup + GRU1 --------------------------------
__global__ void k_gru1(const int* __restrict__ x, const float* __restrict__ hidden,
                       const float* __restrict__ emb, const float* __restrict__ wih,
                       const float* __restrict__ whh, const float* __restrict__ bih,
                       const float* __restrict__ bhh) {
    int b = blockIdx.x, t = threadIdx.x;
    __shared__ __align__(16) float e_sh[256], h_sh[256];
    __shared__ float gi_sh[768], gh_sh[768];
    int tok = x[b];
    float ev = emb[tok * 256 + t];
    e_sh[t] = ev;
    g_emb[b * 256 + t] = ev;
    h_sh[t] = hidden[b * 256 + t];
    __syncthreads();
    int warp = t >> 5, lane = t & 31;
    for (int row = warp; row < 768; row += 8) {
        const float4* wi = (const float4*)(wih + row * 256);
        const float4* wh = (const float4*)(whh + row * 256);
        float si = 0.f, sh = 0.f;
#pragma unroll
        for (int j = 0; j < 2; j++) {
            int idx = lane + j * 32;
            si += dot4(wi[idx], ((float4*)e_sh)[idx]);
            sh += dot4(wh[idx], ((float4*)h_sh)[idx]);
        }
        si = warp_sum(si);
        sh = warp_sum(sh);
        if (!lane) { gi_sh[row] = si + bih[row]; gh_sh[row] = sh + bhh[row]; }
    }
    __syncthreads();
    float r = sigmoidf(gi_sh[t] + gh_sh[t]);
    float z = sigmoidf(gi_sh[256 + t] + gh_sh[256 + t]);
    float n = tanhf(gi_sh[512 + t] + r * gh_sh[512 + t]);
    g_pred[b * 256 + t] = (1.f - z) * n + z * h_sh[t];
}

// ---------------- K2a: transpose Ua_w (512x684) into g_B rows 0..683 ---------
__global__ void k_transpose(const float* __restrict__ Ua) {
    __shared__ float tile[32][33];
    int c0 = blockIdx.x * 32, n0 = blockIdx.y * 32;
    int tx = threadIdx.x, ty = threadIdx.y;
    for (int i = ty; i < 32; i += 8) {
        int c = c0 + tx;
        tile[i][tx] = (c < 684) ? Ua[(n0 + i) * 684 + c] : 0.f;
    }
    __syncthreads();
    for (int i = ty; i < 32; i += 8) {
        int k = c0 + i;
        if (k < 684) g_B[k * 512 + n0 + tx] = tile[tx][i];
    }
}

// ---------------- K2b: W2[kk][n] = sum_q convQ_w[q,kk] * Uf_w[n,q] -----------
__global__ void k_w2(const float* __restrict__ cqw, const float* __restrict__ Ufw) {
    int kk = blockIdx.x;          // 0..131 -> g_B row 684+kk
    int k = 684 + kk;
    __shared__ __align__(16) float col[256];
    if (kk < 121) {
        for (int q = threadIdx.x; q < 256; q += 256) col[q] = cqw[q * 121 + kk];
        __syncthreads();
        int warp = threadIdx.x >> 5, lane = threadIdx.x & 31;
        for (int n = warp; n < 512; n += 8) {
            const float4* uf = (const float4*)(Ufw + n * 256);
            float s = 0.f;
#pragma unroll
            for (int j = 0; j < 2; j++) {
                int idx = lane + j * 32;
                s += dot4(uf[idx], ((float4*)col)[idx]);
            }
            s = warp_sum(s);
            if (!lane) g_B[k * 512 + n] = s;
        }
    } else {
        for (int n = threadIdx.x; n < 512; n += 256) g_B[k * 512 + n] = 0.f;
    }
}

// ---------------- K3: query'[b,p] = pred@Wa^T + Wa_b + Ua_b + Uf_b + Uf@convQ_b
__global__ void k_query(const float* __restrict__ Waw, const float* __restrict__ Wab,
                        const float* __restrict__ Uab, const float* __restrict__ Ufw,
                        const float* __restrict__ Ufb, const float* __restrict__ cqb) {
    int b = blockIdx.x, t = threadIdx.x;
    __shared__ __align__(16) float p_sh[256], c_sh[256];
    p_sh[t] = g_pred[b * 256 + t];
    c_sh[t] = cqb[t];
    __syncthreads();
    int warp = t >> 5, lane = t & 31;
    for (int p = warp; p < 512; p += 8) {
        const float4* wa = (const float4*)(Waw + p * 256);
        const float4* uf = (const float4*)(Ufw + p * 256);
        float s = 0.f;
#pragma unroll
        for (int j = 0; j < 2; j++) {
            int idx = lane + j * 32;
            s += dot4(wa[idx], ((float4*)p_sh)[idx]);
            s += dot4(uf[idx], ((float4*)c_sh)[idx]);
        }
        s = warp_sum(s);
        if (!lane) g_query[b * 512 + p] = s + Wab[p] + Uab[p] + Ufb[p];
    }
}

// ---------------- K4: fused attention GEMM + tanh + Va reduction -------------
// A = [feature_b^T (1024x684) | conv-patches (1024x121)], B = g_B (805x512)
// e_part[b,m] = sum_n Va[n] * tanh(A@B + query'[b,n]); BM=64, BN=256, BK=16
__global__ void __launch_bounds__(256, 2)
k_score(const float* __restrict__ feature, const float* __restrict__ alpha,
        const float* __restrict__ Va) {
    const int b = blockIdx.z;
    const int m0 = blockIdx.x * 64;
    const int n0 = blockIdx.y * 256;
    const int tid = threadIdx.x;
    const int tx = tid & 31, ty = tid >> 5;
    __shared__ __align__(16) float As[16][64];
    __shared__ __align__(16) float Bs[16][256];
    __shared__ __align__(16) float beta_sh[1024];
    __shared__ float red[64 * 33];
    for (int i = tid; i < 1024; i += 256) beta_sh[i] = alpha[b * 1024 + i];
    unsigned long long acc[8][4];
#pragma unroll
    for (int i = 0; i < 8; i++)
#pragma unroll
        for (int j = 0; j < 4; j++) acc[i][j] = 0ull;
    const float* fb = feature + (size_t)b * 684 * 1024;

    for (int kt = 0; kt < 51; kt++) {
        int k0 = kt * 16;
        __syncthreads();
        {   // As tile: 16x64 (one float4 per thread)
            int kk = tid >> 4;
            int m4 = (tid & 15) << 2;
            int k = k0 + kk;
            float4 v;
            if (k < 684) {
                v = *(const float4*)(fb + (size_t)k * 1024 + m0 + m4);
            } else {
                v = make_float4(0.f, 0.f, 0.f, 0.f);
                int kkk = k - 684;
                if (kkk < 121) {
                    int dy = kkk / 11 - 5, dx = kkk % 11 - 5;
                    float tmp[4];
#pragma unroll
                    for (int j = 0; j < 4; j++) {
                        int m = m0 + m4 + j;
                        int y = (m >> 5) + dy, xx = (m & 31) + dx;
                        tmp[j] = (y >= 0 && y < 32 && xx >= 0 && xx < 32)
                                     ? beta_sh[(y << 5) + xx] : 0.f;
                    }
                    v = make_float4(tmp[0], tmp[1], tmp[2], tmp[3]);
                }
            }
            *(float4*)&As[kk][m4] = v;
        }
#pragma unroll
        for (int i = 0; i < 4; i++) {  // Bs tile: 16x256
            int lin = tid + i * 256;
            int kk = lin >> 6;
            int n4 = (lin & 63) << 2;
            *(float4*)&Bs[kk][n4] = *(const float4*)&g_B[(k0 + kk) * 512 + n0 + n4];
        }
        __syncthreads();
#pragma unroll
        for (int kk = 0; kk < 16; kk++) {
            float4 b0 = *(float4*)&Bs[kk][tx * 8];
            float4 b1 = *(float4*)&Bs[kk][tx * 8 + 4];
            unsigned long long bb[4];
            bb[0] = pack2(b0.x, b0.y); bb[1] = pack2(b0.z, b0.w);
            bb[2] = pack2(b1.x, b1.y); bb[3] = pack2(b1.z, b1.w);
            float4 a0 = *(float4*)&As[kk][ty * 8];
            float4 a1 = *(float4*)&As[kk][ty * 8 + 4];
            float av[8] = {a0.x, a0.y, a0.z, a0.w, a1.x, a1.y, a1.z, a1.w};
#pragma unroll
            for (int mi = 0; mi < 8; mi++) {
                unsigned long long ad = pack2(av[mi], av[mi]);
#pragma unroll
                for (int nj = 0; nj < 4; nj++) fma2(acc[mi][nj], ad, bb[nj]);
            }
        }
    }
    // epilogue: + query, tanh, weighted reduce over n
    float va[8], qv[8];
#pragma unroll
    for (int ni = 0; ni < 8; ni++) {
        va[ni] = Va[n0 + tx * 8 + ni];
        qv[ni] = g_query[b * 512 + n0 + tx * 8 + ni];
    }
#pragma unroll
    for (int mi = 0; mi < 8; mi++) {
        float e = 0.f;
#pragma unroll
        for (int nj = 0; nj < 4; nj++) {
            float2 f = unpack2(acc[mi][nj]);
            e += va[nj * 2]     * tanhf(f.x + qv[nj * 2]);
            e += va[nj * 2 + 1] * tanhf(f.y + qv[nj * 2 + 1]);
        }
        red[(ty * 8 + mi) * 33 + tx] = e;
    }
    __syncthreads();
    if (tid < 64) {
        float s = 0.f;
#pragma unroll
        for (int j = 0; j < 32; j++) s += red[tid * 33 + j];
        g_ep[blockIdx.y][b * 1024 + m0 + tid] = s;
    }
}

// ---------------- K5: softmax (exact reference formula, no max-sub) ----------
__global__ void k_softmax(const float* __restrict__ Vab, float* __restrict__ out) {
    int b = blockIdx.x, t = threadIdx.x;
    __shared__ float red[256];
    float vab = Vab[0];
    float ex[4];
    float s = 0.f;
#pragma unroll
    for (int i = 0; i < 4; i++) {
        int idx = b * 1024 + t + i * 256;
        float e = g_ep[0][idx] + g_ep[1][idx] + vab;
        ex[i] = expf(e);
        s += ex[i];
    }
    red[t] = s;
    __syncthreads();
    for (int o = 128; o > 0; o >>= 1) {
        if (t < o) red[t] += red[t + o];
        __syncthreads();
    }
    float denom = red[0] + 1e-8f;
#pragma unroll
    for (int i = 0; i < 4; i++)
        out[ALPHA_OFF + b * 1024 + t + i * 256] = ex[i] / denom;
}

// ---------------- K6: context[b,c] = feature[b,c,:] . alpha_t[b,:] -----------
__global__ void k_context(const float* __restrict__ feature,
                          const float* __restrict__ out) {
    int b = blockIdx.y;
    int c = blockIdx.x * 8 + (threadIdx.x >> 5);
    int lane = threadIdx.x & 31;
    if (c >= 684) return;
    const float4* f = (const float4*)(feature + (size_t)b * 684 * 1024 + (size_t)c * 1024);
    const float4* a = (const float4*)(out + ALPHA_OFF + b * 1024);
    float s = 0.f;
#pragma unroll
    for (int j = 0; j < 8; j++) {
        int idx = lane + j * 32;
        s += dot4(f[idx], a[idx]);
    }
    s = warp_sum(s);
    if (!lane) g_ctx[b * 684 + c] = s;
}

// ---------------- K7a: GRU2(context, pred) -> h2 (written to d_out) ----------
__global__ void k_gru2(const float* __restrict__ wih, const float* __restrict__ whh,
                       const float* __restrict__ bih, const float* __restrict__ bhh,
                       float* __restrict__ out) {
    int b = blockIdx.x, t = threadIdx.x;
    __shared__ __align__(16) float x_sh[684], h_sh[256];
    __shared__ float gi_sh[768], gh_sh[768];
    for (int i = t; i < 684; i += 256) x_sh[i] = g_ctx[b * 684 + i];
    h_sh[t] = g_pred[b * 256 + t];
    __syncthreads();
    int warp = t >> 5, lane = t & 31;
    for (int row = warp; row < 768; row += 8) {
        const float4* wi = (const float4*)(wih + row * 684);
        const float4* wh = (const float4*)(whh + row * 256);
        float si = 0.f, sh = 0.f;
#pragma unroll
        for (int j = 0; j < 6; j++) {
            int idx = lane + j * 32;
            if (idx < 171) si += dot4(wi[idx], ((float4*)x_sh)[idx]);
        }
#pragma unroll
        for (int j = 0; j < 2; j++) {
            int idx = lane + j * 32;
            sh += dot4(wh[idx], ((float4*)h_sh)[idx]);
        }
        si = warp_sum(si);
        sh = warp_sum(sh);
        if (!lane) { gi_sh[row] = si + bih[row]; gh_sh[row] = sh + bhh[row]; }
    }
    __syncthreads();
    float r = sigmoidf(gi_sh[t] + gh_sh[t]);
    float z = sigmoidf(gi_sh[256 + t] + gh_sh[256 + t]);
    float n = tanhf(gi_sh[512 + t] + r * gh_sh[512 + t]);
    out[H2_OFF + b * 256 + t] = (1.f - z) * n + z * h_sh[t];
}

// ---------------- K7b: o = emb + h2@Ws^T + ctx@Wc^T; maxout; logits ----------
__global__ void k_out(const float* __restrict__ Wsw, const float* __restrict__ Wsb,
                      const float* __restrict__ Wcw, const float* __restrict__ Wcb,
                      const float* __restrict__ Wow, const float* __restrict__ Wob,
                      float* __restrict__ out) {
    int b = blockIdx.x, t = threadIdx.x;
    __shared__ __align__(16) float h_sh[256], x_sh[684], o_sh[256], mo_sh[128];
    h_sh[t] = out[H2_OFF + b * 256 + t];
    for (int i = t; i < 684; i += 256) x_sh[i] = g_ctx[b * 684 + i];
    __syncthreads();
    int warp = t >> 5, lane = t & 31;
    for (int row = warp; row < 256; row += 8) {
        const float4* ws = (const float4*)(Wsw + row * 256);
        const float4* wc = (const float4*)(Wcw + row * 684);
        float s = 0.f;
#pragma unroll
        for (int j = 0; j < 2; j++) {
            int idx = lane + j * 32;
            s += dot4(ws[idx], ((float4*)h_sh)[idx]);
        }
#pragma unroll
        for (int j = 0; j < 6; j++) {
            int idx = lane + j * 32;
            if (idx < 171) s += dot4(wc[idx], ((float4*)x_sh)[idx]);
        }
        s = warp_sum(s);
        if (!lane) o_sh[row] = g_emb[b * 256 + row] + s + Wsb[row] + Wcb[row];
    }
    __syncthreads();
    if (t < 128) mo_sh[t] = fmaxf(o_sh[2 * t], o_sh[2 * t + 1]);
    __syncthreads();
    for (int row = warp; row < 128; row += 8) {
        const float4* wo = (const float4*)(Wow + row * 128);
        float s = dot4(wo[lane], ((float4*)mo_sh)[lane]);
        s = warp_sum(s);
        if (!lane) out[LOGITS_OFF + b * 128 + row] = s + Wob[row];
    }
}

// ---------------- launch ------------------------------------------------------
extern "C" void kernel_launch(void* const* d_in, const int* in_sizes, int n_in,
                              void* d_out, int out_size) {
    const int*   x       = (const int*)d_in[0];
    const float* hidden  = (const float*)d_in[1];
    const float* feature = (const float*)d_in[2];
    const float* alpha   = (const float*)d_in[3];
    const float* emb     = (const float*)d_in[4];
    const float* g1wih   = (const float*)d_in[5];
    const float* g1whh   = (const float*)d_in[6];
    const float* g1bih   = (const float*)d_in[7];
    const float* g1bhh   = (const float*)d_in[8];
    const float* g2wih   = (const float*)d_in[9];
    const float* g2whh   = (const float*)d_in[10];
    const float* g2bih   = (const float*)d_in[11];
    const float* g2bhh   = (const float*)d_in[12];
    const float* cqw     = (const float*)d_in[13];
    const float* cqb     = (const float*)d_in[14];
    const float* Waw     = (const float*)d_in[15];
    const float* Wab     = (const float*)d_in[16];
    const float* Uaw     = (const float*)d_in[17];
    const float* Uab     = (const float*)d_in[18];
    const float* Ufw     = (const float*)d_in[19];
    const float* Ufb     = (const float*)d_in[20];
    const float* Vaw     = (const float*)d_in[21];
    const float* Vab     = (const float*)d_in[22];
    const float* Wsw     = (const float*)d_in[23];
    const float* Wsb     = (const float*)d_in[24];
    const float* Wcw     = (const float*)d_in[25];
    const float* Wcb     = (const float*)d_in[26];
    const float* Wow     = (const float*)d_in[27];
    const float* Wob     = (const float*)d_in[28];
    float* out = (float*)d_out;

    k_gru1<<<64, 256>>>(x, hidden, emb, g1wih, g1whh, g1bih, g1bhh);
    k_transpose<<<dim3(22, 16), dim3(32, 8)>>>(Uaw);
    k_w2<<<132, 256>>>(cqw, Ufw);
    k_query<<<64, 256>>>(Waw, Wab, Uab, Ufw, Ufb, cqb);
    k_score<<<dim3(16, 2, 64), 256>>>(feature, alpha, Vaw);
    k_softmax<<<64, 256>>>(Vab, out);
    k_context<<<dim3(86, 64), 256>>>(feature, out);
    k_gru2<<<64, 256>>>(g2wih, g2whh, g2bih, g2bhh, out);
    k_out<<<64, 256>>>(Wsw, Wsb, Wcw, Wcb, Wow, Wob, out);
}

// round 5
// speedup vs baseline: 1.9656x; 1.9656x over previous
#include <cuda_runtime.h>
#include <math.h>
#include <stdint.h>

#define LOGITS_OFF 0
#define H2_OFF     8192
#define ALPHA_OFF  24576

// ---------------- scratch ----------------------------------------------------
__device__ float g_emb  [64 * 256];
__device__ float g_pred [64 * 256];
__device__ float g_query[64 * 512];
__device__ float g_B    [832 * 512];    // [k][n] k-major, tf32-rounded, K padded
__device__ float g_ep   [2][64 * 1024]; // n-half partials (deterministic merge)
__device__ float g_ctx  [64 * 684];

// ---------------- helpers -----------------------------------------------------
__device__ __forceinline__ float warp_sum(float v) {
#pragma unroll
    for (int o = 16; o; o >>= 1) v += __shfl_down_sync(0xffffffffu, v, o);
    return v;
}
__device__ __forceinline__ float sigmoidf(float x) { return 1.f / (1.f + expf(-x)); }
__device__ __forceinline__ float dot4(float4 a, float4 b) {
    return a.x * b.x + a.y * b.y + a.z * b.z + a.w * b.w;
}
__device__ __forceinline__ uint32_t to_tf32_bits(float f) {
    uint32_t r;
    asm("cvt.rna.tf32.f32 %0, %1;" : "=r"(r) : "f"(f));
    return r;
}
__device__ __forceinline__ float tf32f(float f) { return __uint_as_float(to_tf32_bits(f)); }
__device__ __forceinline__ float tanh_fast(float x) {
    float y;
    asm("tanh.approx.f32 %0, %1;" : "=f"(y) : "f"(x));
    return y;
}
// mma.sync m16n8k8 tf32 (baseline PTX — no sm_103a-only features)
__device__ __forceinline__ void mma_tf32(float* c, const uint32_t* a, uint32_t b0,
                                         uint32_t b1) {
    asm volatile(
        "mma.sync.aligned.m16n8k8.row.col.f32.tf32.tf32.f32 "
        "{%0,%1,%2,%3}, {%4,%5,%6,%7}, {%8,%9}, {%0,%1,%2,%3};"
        : "+f"(c[0]), "+f"(c[1]), "+f"(c[2]), "+f"(c[3])
        : "r"(a[0]), "r"(a[1]), "r"(a[2]), "r"(a[3]), "r"(b0), "r"(b1));
}

// ---------------- K1: embedding + GRU1 ----------------------------------------
__global__ void k_gru1(const int* __restrict__ x, const float* __restrict__ hidden,
                       const float* __restrict__ emb, const float* __restrict__ wih,
                       const float* __restrict__ whh, const float* __restrict__ bih,
                       const float* __restrict__ bhh) {
    int b = blockIdx.x, t = threadIdx.x;
    __shared__ __align__(16) float e_sh[256], h_sh[256];
    __shared__ float gi_sh[768], gh_sh[768];
    int tok = x[b];
    float ev = emb[tok * 256 + t];
    e_sh[t] = ev;
    g_emb[b * 256 + t] = ev;
    h_sh[t] = hidden[b * 256 + t];
    __syncthreads();
    int warp = t >> 5, lane = t & 31;
    for (int row = warp; row < 768; row += 8) {
        const float4* wi = (const float4*)(wih + row * 256);
        const float4* wh = (const float4*)(whh + row * 256);
        float si = 0.f, sh = 0.f;
#pragma unroll
        for (int j = 0; j < 2; j++) {
            int idx = lane + j * 32;
            si += dot4(wi[idx], ((float4*)e_sh)[idx]);
            sh += dot4(wh[idx], ((float4*)h_sh)[idx]);
        }
        si = warp_sum(si);
        sh = warp_sum(sh);
        if (!lane) { gi_sh[row] = si + bih[row]; gh_sh[row] = sh + bhh[row]; }
    }
    __syncthreads();
    float r = sigmoidf(gi_sh[t] + gh_sh[t]);
    float z = sigmoidf(gi_sh[256 + t] + gh_sh[256 + t]);
    float n = tanhf(gi_sh[512 + t] + r * gh_sh[512 + t]);
    g_pred[b * 256 + t] = (1.f - z) * n + z * h_sh[t];
}

// ---------------- prep: g_B[k][n] = tf32(Ua^T) (rows 0..683) -------------------
__global__ void k_transpose(const float* __restrict__ Ua) {
    __shared__ float tile[32][33];
    int c0 = blockIdx.x * 32, n0 = blockIdx.y * 32;
    int tx = threadIdx.x, ty = threadIdx.y;
    for (int i = ty; i < 32; i += 8) {
        int c = c0 + tx;
        tile[i][tx] = (c < 684) ? Ua[(n0 + i) * 684 + c] : 0.f;
    }
    __syncthreads();
    for (int i = ty; i < 32; i += 8) {
        int k = c0 + i;
        if (k < 684) g_B[k * 512 + n0 + tx] = tf32f(tile[tx][i]);
    }
}

// ---------------- prep: conv rows 684..804, zero 805..831 ----------------------
__global__ void k_w2(const float* __restrict__ cqw, const float* __restrict__ Ufw) {
    int kk = blockIdx.x;          // 0..147
    int k = 684 + kk;
    __shared__ __align__(16) float col[256];
    if (kk < 121) {
        for (int q = threadIdx.x; q < 256; q += 256) col[q] = cqw[q * 121 + kk];
        __syncthreads();
        int warp = threadIdx.x >> 5, lane = threadIdx.x & 31;
        for (int n = warp; n < 512; n += 8) {
            const float4* uf = (const float4*)(Ufw + n * 256);
            float s = 0.f;
#pragma unroll
            for (int j = 0; j < 2; j++) {
                int idx = lane + j * 32;
                s += dot4(uf[idx], ((float4*)col)[idx]);
            }
            s = warp_sum(s);
            if (!lane) g_B[k * 512 + n] = tf32f(s);
        }
    } else {
        for (int n = threadIdx.x; n < 512; n += 256) g_B[k * 512 + n] = 0.f;
    }
}

// ---------------- K3: query' ---------------------------------------------------
__global__ void k_query(const float* __restrict__ Waw, const float* __restrict__ Wab,
                        const float* __restrict__ Uab, const float* __restrict__ Ufw,
                        const float* __restrict__ Ufb, const float* __restrict__ cqb) {
    int b = blockIdx.x, t = threadIdx.x;
    int p0 = blockIdx.y * 128;
    __shared__ __align__(16) float p_sh[256], c_sh[256];
    p_sh[t] = g_pred[b * 256 + t];
    c_sh[t] = cqb[t];
    __syncthreads();
    int warp = t >> 5, lane = t & 31;
    for (int p = p0 + warp; p < p0 + 128; p += 8) {
        const float4* wa = (const float4*)(Waw + p * 256);
        const float4* uf = (const float4*)(Ufw + p * 256);
        float s = 0.f;
#pragma unroll
        for (int j = 0; j < 2; j++) {
            int idx = lane + j * 32;
            s += dot4(wa[idx], ((float4*)p_sh)[idx]);
            s += dot4(uf[idx], ((float4*)c_sh)[idx]);
        }
        s = warp_sum(s);
        if (!lane) g_query[b * 512 + p] = s + Wab[p] + Uab[p] + Ufb[p];
    }
}

// ---------------- K4: fused attention GEMM via mma.sync tf32 --------------------
// grid (8 m-tiles, 2 n-halves, 64 b), 512 threads (16 warps, 4m x 4n),
// warp tile 32x64, BK=16, 52 stages, SINGLE-buffer SMEM + register prefetch.
// SMEM: A 10.2KB + B 16.6KB + beta 4KB + q/va 2KB + red 2KB = 35.1KB (< 48KB).
#define NSTAGE 52
#define A_STR  20                 // As[m][20] floats (conflict-free frag loads)
#define B_STR  260                // Bs[k][260] floats
#define A_STAGE_F (128 * A_STR)   // 2560
#define B_STAGE_F (16 * B_STR)    // 4160

__global__ void __launch_bounds__(512, 1)
k_score_mma(const float* __restrict__ feature, const float* __restrict__ alpha,
            const float* __restrict__ Va) {
    __shared__ __align__(16) float Ash[A_STAGE_F];
    __shared__ __align__(16) float Bsh[B_STAGE_F];
    __shared__ float beta_sh[1024];
    __shared__ float q_s[256], va_s[256];
    __shared__ float red[4][128];

    const int tid = threadIdx.x;
    const int wid = tid >> 5;
    const int lane = tid & 31;
    const int g = lane >> 2, t4 = lane & 3;
    const int warp_m = wid & 3, warp_n = wid >> 2;
    const int rm = warp_m * 32;
    const int cn = warp_n * 64;
    const int b = blockIdx.z;
    const int m0 = blockIdx.x * 128;
    const int n0 = blockIdx.y * 256;
    const float* fb = feature + (size_t)b * 684 * 1024;

    for (int i = tid; i < 1024; i += 512) beta_sh[i] = alpha[b * 1024 + i];
    if (tid < 256) {
        q_s[tid] = g_query[b * 512 + n0 + tid];
        va_s[tid] = Va[n0 + tid];
    }
    __syncthreads();

    // ---- stage 0 load ----
    {
#pragma unroll
        for (int j = 0; j < 2; j++) {
            int idx = tid + j * 512;
            int k = idx >> 6, n4 = (idx & 63) << 2;
            *(float4*)&Bsh[k * B_STR + n4] = *(const float4*)&g_B[k * 512 + n0 + n4];
        }
#pragma unroll
        for (int j = 0; j < 4; j++) {
            int idx = tid + j * 512;
            int k = idx >> 7, m = idx & 127;
            Ash[m * A_STR + k] = tf32f(fb[(size_t)k * 1024 + m0 + m]);
        }
    }
    __syncthreads();

    float acc[2][8][4];
#pragma unroll
    for (int mi = 0; mi < 2; mi++)
#pragma unroll
        for (int ni = 0; ni < 8; ni++)
#pragma unroll
            for (int r = 0; r < 4; r++) acc[mi][ni][r] = 0.f;

    for (int kt = 0; kt < NSTAGE; kt++) {
        const bool have = (kt + 1 < NSTAGE);
        float4 bpre[2];
        float apre[4];
        if (have) {  // prefetch next stage into registers (hidden under mma)
            const int k0n = (kt + 1) * 16;
#pragma unroll
            for (int j = 0; j < 2; j++) {
                int idx = tid + j * 512;
                int k = idx >> 6, n4 = (idx & 63) << 2;
                bpre[j] = *(const float4*)&g_B[(k0n + k) * 512 + n0 + n4];
            }
#pragma unroll
            for (int j = 0; j < 4; j++) {
                int idx = tid + j * 512;
                int k = idx >> 7, m = idx & 127;
                int kg = k0n + k;
                float v;
                if (kg < 684) {
                    v = fb[(size_t)kg * 1024 + m0 + m];
                } else if (kg < 805) {
                    int kk = kg - 684;
                    int dy = kk / 11 - 5, dx = kk % 11 - 5;
                    int mg = m0 + m;
                    int y = (mg >> 5) + dy, xx = (mg & 31) + dx;
                    v = (y >= 0 && y < 32 && xx >= 0 && xx < 32)
                            ? beta_sh[(y << 5) + xx] : 0.f;
                } else {
                    v = 0.f;
                }
                apre[j] = v;
            }
        }
        // ---- compute current stage from SMEM ----
#pragma unroll
        for (int ks = 0; ks < 2; ks++) {
            uint32_t a[2][4];
#pragma unroll
            for (int mi = 0; mi < 2; mi++) {
                int row = rm + mi * 16 + g;
                int col = ks * 8 + t4;
                a[mi][0] = __float_as_uint(Ash[row * A_STR + col]);
                a[mi][1] = __float_as_uint(Ash[(row + 8) * A_STR + col]);
                a[mi][2] = __float_as_uint(Ash[row * A_STR + col + 4]);
                a[mi][3] = __float_as_uint(Ash[(row + 8) * A_STR + col + 4]);
            }
#pragma unroll
            for (int ni = 0; ni < 8; ni++) {
                int nc = cn + ni * 8 + g;
                uint32_t b0 = __float_as_uint(Bsh[(ks * 8 + t4) * B_STR + nc]);
                uint32_t b1 = __float_as_uint(Bsh[(ks * 8 + t4 + 4) * B_STR + nc]);
                mma_tf32(acc[0][ni], a[0], b0, b1);
                mma_tf32(acc[1][ni], a[1], b0, b1);
            }
        }
        __syncthreads();
        if (have) {  // store prefetched stage
#pragma unroll
            for (int j = 0; j < 2; j++) {
                int idx = tid + j * 512;
                int k = idx >> 6, n4 = (idx & 63) << 2;
                *(float4*)&Bsh[k * B_STR + n4] = bpre[j];
            }
#pragma unroll
            for (int j = 0; j < 4; j++) {
                int idx = tid + j * 512;
                int k = idx >> 7, m = idx & 127;
                Ash[m * A_STR + k] = tf32f(apre[j]);
            }
            __syncthreads();
        }
    }

    // ---- epilogue: e[m] = sum_n va[n] * tanh(acc + q[n]) ----
#pragma unroll
    for (int mi = 0; mi < 2; mi++) {
        float e0 = 0.f, e1 = 0.f;
#pragma unroll
        for (int ni = 0; ni < 8; ni++) {
            int c = cn + ni * 8 + 2 * t4;
            float va0 = va_s[c], va1 = va_s[c + 1];
            float q0 = q_s[c], q1 = q_s[c + 1];
            e0 += va0 * tanh_fast(acc[mi][ni][0] + q0)
                + va1 * tanh_fast(acc[mi][ni][1] + q1);
            e1 += va0 * tanh_fast(acc[mi][ni][2] + q0)
                + va1 * tanh_fast(acc[mi][ni][3] + q1);
        }
        e0 += __shfl_xor_sync(0xffffffffu, e0, 1);
        e0 += __shfl_xor_sync(0xffffffffu, e0, 2);
        e1 += __shfl_xor_sync(0xffffffffu, e1, 1);
        e1 += __shfl_xor_sync(0xffffffffu, e1, 2);
        if (t4 == 0) {
            red[warp_n][rm + mi * 16 + g] = e0;
            red[warp_n][rm + mi * 16 + 8 + g] = e1;
        }
    }
    __syncthreads();
    if (tid < 128)
        g_ep[blockIdx.y][b * 1024 + m0 + tid] =
            red[0][tid] + red[1][tid] + red[2][tid] + red[3][tid];
}

// ---------------- K5: softmax ---------------------------------------------------
__global__ void k_softmax(const float* __restrict__ Vab, float* __restrict__ out) {
    int b = blockIdx.x, t = threadIdx.x;
    __shared__ float red[256];
    float vab = Vab[0];
    float ex[4];
    float s = 0.f;
#pragma unroll
    for (int i = 0; i < 4; i++) {
        int idx = b * 1024 + t + i * 256;
        ex[i] = expf(g_ep[0][idx] + g_ep[1][idx] + vab);
        s += ex[i];
    }
    red[t] = s;
    __syncthreads();
    for (int o = 128; o > 0; o >>= 1) {
        if (t < o) red[t] += red[t + o];
        __syncthreads();
    }
    float denom = red[0] + 1e-8f;
#pragma unroll
    for (int i = 0; i < 4; i++)
        out[ALPHA_OFF + b * 1024 + t + i * 256] = ex[i] / denom;
}

// ---------------- K6: context ----------------------------------------------------
__global__ void k_context(const float* __restrict__ feature,
                          const float* __restrict__ out) {
    int b = blockIdx.y;
    int c = blockIdx.x * 8 + (threadIdx.x >> 5);
    int lane = threadIdx.x & 31;
    if (c >= 684) return;
    const float4* f = (const float4*)(feature + (size_t)b * 684 * 1024 + (size_t)c * 1024);
    const float4* a = (const float4*)(out + ALPHA_OFF + b * 1024);
    float s = 0.f;
#pragma unroll
    for (int j = 0; j < 8; j++) {
        int idx = lane + j * 32;
        s += dot4(f[idx], a[idx]);
    }
    s = warp_sum(s);
    if (!lane) g_ctx[b * 684 + c] = s;
}

// ---------------- K7a: GRU2 -------------------------------------------------------
__global__ void k_gru2(const float* __restrict__ wih, const float* __restrict__ whh,
                       const float* __restrict__ bih, const float* __restrict__ bhh,
                       float* __restrict__ out) {
    int b = blockIdx.x, t = threadIdx.x;
    __shared__ __align__(16) float x_sh[684], h_sh[256];
    __shared__ float gi_sh[768], gh_sh[768];
    for (int i = t; i < 684; i += 256) x_sh[i] = g_ctx[b * 684 + i];
    h_sh[t] = g_pred[b * 256 + t];
    __syncthreads();
    int warp = t >> 5, lane = t & 31;
    for (int row = warp; row < 768; row += 8) {
        const float4* wi = (const float4*)(wih + row * 684);
        const float4* wh = (const float4*)(whh + row * 256);
        float si = 0.f, sh = 0.f;
#pragma unroll
        for (int j = 0; j < 6; j++) {
            int idx = lane + j * 32;
            if (idx < 171) si += dot4(wi[idx], ((float4*)x_sh)[idx]);
        }
#pragma unroll
        for (int j = 0; j < 2; j++) {
            int idx = lane + j * 32;
            sh += dot4(wh[idx], ((float4*)h_sh)[idx]);
        }
        si = warp_sum(si);
        sh = warp_sum(sh);
        if (!lane) { gi_sh[row] = si + bih[row]; gh_sh[row] = sh + bhh[row]; }
    }
    __syncthreads();
    float r = sigmoidf(gi_sh[t] + gh_sh[t]);
    float z = sigmoidf(gi_sh[256 + t] + gh_sh[256 + t]);
    float n = tanhf(gi_sh[512 + t] + r * gh_sh[512 + t]);
    out[H2_OFF + b * 256 + t] = (1.f - z) * n + z * h_sh[t];
}

// ---------------- K7b: output head -------------------------------------------------
__global__ void k_out(const float* __restrict__ Wsw, const float* __restrict__ Wsb,
                      const float* __restrict__ Wcw, const float* __restrict__ Wcb,
                      const float* __restrict__ Wow, const float* __restrict__ Wob,
                      float* __restrict__ out) {
    int b = blockIdx.x, t = threadIdx.x;
    __shared__ __align__(16) float h_sh[256], x_sh[684], o_sh[256], mo_sh[128];
    h_sh[t] = out[H2_OFF + b * 256 + t];
    for (int i = t; i < 684; i += 256) x_sh[i] = g_ctx[b * 684 + i];
    __syncthreads();
    int warp = t >> 5, lane = t & 31;
    for (int row = warp; row < 256; row += 8) {
        const float4* ws = (const float4*)(Wsw + row * 256);
        const float4* wc = (const float4*)(Wcw + row * 684);
        float s = 0.f;
#pragma unroll
        for (int j = 0; j < 2; j++) {
            int idx = lane + j * 32;
            s += dot4(ws[idx], ((float4*)h_sh)[idx]);
        }
#pragma unroll
        for (int j = 0; j < 6; j++) {
            int idx = lane + j * 32;
            if (idx < 171) s += dot4(wc[idx], ((float4*)x_sh)[idx]);
        }
        s = warp_sum(s);
        if (!lane) o_sh[row] = g_emb[b * 256 + row] + s + Wsb[row] + Wcb[row];
    }
    __syncthreads();
    if (t < 128) mo_sh[t] = fmaxf(o_sh[2 * t], o_sh[2 * t + 1]);
    __syncthreads();
    for (int row = warp; row < 128; row += 8) {
        const float4* wo = (const float4*)(Wow + row * 128);
        float s = dot4(wo[lane], ((float4*)mo_sh)[lane]);
        s = warp_sum(s);
        if (!lane) out[LOGITS_OFF + b * 128 + row] = s + Wob[row];
    }
}

// ---------------- launch -------------------------------------------------------------
extern "C" void kernel_launch(void* const* d_in, const int* in_sizes, int n_in,
                              void* d_out, int out_size) {
    const int*   x       = (const int*)d_in[0];
    const float* hidden  = (const float*)d_in[1];
    const float* feature = (const float*)d_in[2];
    const float* alpha   = (const float*)d_in[3];
    const float* emb     = (const float*)d_in[4];
    const float* g1wih   = (const float*)d_in[5];
    const float* g1whh   = (const float*)d_in[6];
    const float* g1bih   = (const float*)d_in[7];
    const float* g1bhh   = (const float*)d_in[8];
    const float* g2wih   = (const float*)d_in[9];
    const float* g2whh   = (const float*)d_in[10];
    const float* g2bih   = (const float*)d_in[11];
    const float* g2bhh   = (const float*)d_in[12];
    const float* cqw     = (const float*)d_in[13];
    const float* cqb     = (const float*)d_in[14];
    const float* Waw     = (const float*)d_in[15];
    const float* Wab     = (const float*)d_in[16];
    const float* Uaw     = (const float*)d_in[17];
    const float* Uab     = (const float*)d_in[18];
    const float* Ufw     = (const float*)d_in[19];
    const float* Ufb     = (const float*)d_in[20];
    const float* Vaw     = (const float*)d_in[21];
    const float* Vab     = (const float*)d_in[22];
    const float* Wsw     = (const float*)d_in[23];
    const float* Wsb     = (const float*)d_in[24];
    const float* Wcw     = (const float*)d_in[25];
    const float* Wcb     = (const float*)d_in[26];
    const float* Wow     = (const float*)d_in[27];
    const float* Wob     = (const float*)d_in[28];
    float* out = (float*)d_out;

    k_gru1<<<64, 256>>>(x, hidden, emb, g1wih, g1whh, g1bih, g1bhh);
    k_transpose<<<dim3(22, 16), dim3(32, 8)>>>(Uaw);
    k_w2<<<148, 256>>>(cqw, Ufw);
    k_query<<<dim3(64, 4), 256>>>(Waw, Wab, Uab, Ufw, Ufb, cqb);
    k_score_mma<<<dim3(8, 2, 64), 512>>>(feature, alpha, Vaw);
    k_softmax<<<64, 256>>>(Vab, out);
    k_context<<<dim3(86, 64), 256>>>(feature, out);
    k_gru2<<<64, 256>>>(g2wih, g2whh, g2bih, g2bhh, out);
    k_out<<<64, 256>>>(Wsw, Wsb, Wcw, Wcb, Wow, Wob, out);
}